// round 2
// baseline (speedup 1.0000x reference)
#include <cuda_runtime.h>
#include <cuda_bf16.h>
#include <stdint.h>

// ---------------- static scratch (no allocation allowed) ----------------
#define N_MAX 100352          // >= N=100000, multiple of 64
#define F 128                 // feature dim (IN=HID=OUT=128)

__device__ __align__(16) static float g_g[(size_t)N_MAX * F];    // pre-scaled transformed features
__device__ __align__(16) static float g_acc[(size_t)N_MAX * F];  // scatter accumulator / h1
__device__ __align__(16) static float g_dis[N_MAX];
__device__ static int   g_degc[N_MAX];
__device__ static int   g_counts[1024];
__device__ static int   g_e64;   // 1 if edge_index is int64
__device__ static int   g_b64;   // 1 if batch is int64

// ---------------- dtype detection ----------------
// If the logical-int64 array actually holds int64 (values < 2^31), every odd
// 32-bit word is 0. If it is int32, odd words are real (nonzero w.h.p.) values.
__global__ void detect_kernel(const int* __restrict__ a, int nwords, int which) {
    __shared__ int any;
    if (threadIdx.x == 0) any = 0;
    __syncthreads();
    int local = 0;
    for (int i = 1 + 2 * (int)threadIdx.x; i < nwords; i += 2 * (int)blockDim.x)
        local |= a[i];
    if (local) atomicOr(&any, 1);
    __syncthreads();
    if (threadIdx.x == 0) {
        int is64 = (any == 0) ? 1 : 0;
        if (which == 0) g_e64 = is64; else g_b64 = is64;
    }
}

__device__ __forceinline__ long long load_idx(const void* p, long long i, int is64) {
    if (is64) return ((const long long*)p)[i];
    return (long long)((const int*)p)[i];
}

// ---------------- zero fill ----------------
__global__ void zero_kernel(float* __restrict__ p, long long n) {   // n multiple of 4
    long long i = (long long)blockIdx.x * blockDim.x + threadIdx.x;
    if (i * 4 < n) {
        float4 z = make_float4(0.f, 0.f, 0.f, 0.f);
        *(float4*)(p + i * 4) = z;
    }
}

// ---------------- degree / dis ----------------
__global__ void deg_kernel(const void* __restrict__ edge, int E) {
    int e = blockIdx.x * blockDim.x + threadIdx.x;
    if (e >= E) return;
    int is64 = g_e64;
    long long dst = load_idx(edge, (long long)E + e, is64);
    atomicAdd(&g_degc[dst], 1);
}

__global__ void dis_kernel(int n) {
    int i = blockIdx.x * blockDim.x + threadIdx.x;
    if (i >= n) return;
    g_dis[i] = rsqrtf((float)(g_degc[i] + 1));   // +1 self loop, always > 0
}

// ---------------- GEMM: C[i][:] = (A[i][:] @ W) * dis[i] ----------------
// tile: 64 rows x 128 cols, block = 256 threads. W streamed via L1.
__global__ void __launch_bounds__(256) gemm_scale_kernel(
    const float* __restrict__ A, const float* __restrict__ W,
    float* __restrict__ C, int n)
{
    __shared__ float As[64 * F];
    int t = threadIdx.x;
    int row0 = blockIdx.x * 64;

    // stage A tile (zero-pad past n)
    for (int i = t; i < 64 * F / 4; i += 256) {
        int lin = i * 4;
        int r = lin >> 7;
        int c = lin & 127;
        float4 v = make_float4(0.f, 0.f, 0.f, 0.f);
        if (row0 + r < n) v = *(const float4*)&A[(size_t)(row0 + r) * F + c];
        *(float4*)&As[lin] = v;
    }
    __syncthreads();

    int tx = t & 31;        // 4-col group -> cols [tx*4, tx*4+3]
    int ty = t >> 5;        // 8-row group -> rows [ty*8, ty*8+7]

    float acc[8][4];
#pragma unroll
    for (int r = 0; r < 8; r++)
#pragma unroll
        for (int c = 0; c < 4; c++) acc[r][c] = 0.f;

#pragma unroll 2
    for (int k0 = 0; k0 < F; k0 += 4) {
        float4 w0 = __ldg((const float4*)&W[(size_t)(k0 + 0) * F + tx * 4]);
        float4 w1 = __ldg((const float4*)&W[(size_t)(k0 + 1) * F + tx * 4]);
        float4 w2 = __ldg((const float4*)&W[(size_t)(k0 + 2) * F + tx * 4]);
        float4 w3 = __ldg((const float4*)&W[(size_t)(k0 + 3) * F + tx * 4]);
#pragma unroll
        for (int r = 0; r < 8; r++) {
            float4 a = *(const float4*)&As[(ty * 8 + r) * F + k0];
            acc[r][0] += a.x * w0.x + a.y * w1.x + a.z * w2.x + a.w * w3.x;
            acc[r][1] += a.x * w0.y + a.y * w1.y + a.z * w2.y + a.w * w3.y;
            acc[r][2] += a.x * w0.z + a.y * w1.z + a.z * w2.z + a.w * w3.z;
            acc[r][3] += a.x * w0.w + a.y * w1.w + a.z * w2.w + a.w * w3.w;
        }
    }

#pragma unroll
    for (int r = 0; r < 8; r++) {
        int row = row0 + ty * 8 + r;
        if (row < n) {
            float s = g_dis[row];
            float4 o = make_float4(acc[r][0] * s, acc[r][1] * s, acc[r][2] * s, acc[r][3] * s);
            *(float4*)&C[(size_t)row * F + tx * 4] = o;
        }
    }
}

// ---------------- edge scatter: acc[dst] += g[src] ----------------
__global__ void __launch_bounds__(256) scatter_kernel(
    const float* __restrict__ g, float* __restrict__ acc,
    const void* __restrict__ edge, int E)
{
    int w = (blockIdx.x * blockDim.x + threadIdx.x) >> 5;
    int lane = threadIdx.x & 31;
    if (w >= E) return;
    int is64 = g_e64;
    long long src = load_idx(edge, w, is64);
    long long dst = load_idx(edge, (long long)E + w, is64);
    float4 v = *(const float4*)&g[(size_t)src * F + lane * 4];
    float* p = &acc[(size_t)dst * F + lane * 4];
    asm volatile("red.global.add.v4.f32 [%0], {%1,%2,%3,%4};"
                 :: "l"(p), "f"(v.x), "f"(v.y), "f"(v.z), "f"(v.w) : "memory");
}

// ---------------- layer epilogue 1: h1 = relu(dis*(acc+g) + b)  (in place into acc) ----------------
__global__ void finish1_kernel(const float* __restrict__ b, int n) {
    int i = blockIdx.x * blockDim.x + threadIdx.x;   // one float4 group
    if (i >= n * 32) return;
    int node = i >> 5;
    int c = (i & 31) * 4;
    float4 a = *(float4*)&g_acc[(size_t)i * 4];
    float4 gg = *(const float4*)&g_g[(size_t)i * 4];
    float d = g_dis[node];
    float4 bb = *(const float4*)&b[c];
    float4 o;
    o.x = fmaxf(fmaf(d, a.x + gg.x, bb.x), 0.f);
    o.y = fmaxf(fmaf(d, a.y + gg.y, bb.y), 0.f);
    o.z = fmaxf(fmaf(d, a.z + gg.z, bb.z), 0.f);
    o.w = fmaxf(fmaf(d, a.w + gg.w, bb.w), 0.f);
    *(float4*)&g_acc[(size_t)i * 4] = o;
}

// ---------------- layer epilogue 2 + mean-pool scatter ----------------
__global__ void finish2_kernel(const void* __restrict__ batch, const float* __restrict__ b,
                               float* __restrict__ out, int n) {
    int i = blockIdx.x * blockDim.x + threadIdx.x;
    if (i >= n * 32) return;
    int node = i >> 5;
    int c = (i & 31) * 4;
    float4 a = *(float4*)&g_acc[(size_t)i * 4];
    float4 gg = *(const float4*)&g_g[(size_t)i * 4];
    float d = g_dis[node];
    float4 bb = *(const float4*)&b[c];
    float4 o;
    o.x = fmaxf(fmaf(d, a.x + gg.x, bb.x), 0.f);
    o.y = fmaxf(fmaf(d, a.y + gg.y, bb.y), 0.f);
    o.z = fmaxf(fmaf(d, a.z + gg.z, bb.z), 0.f);
    o.w = fmaxf(fmaf(d, a.w + gg.w, bb.w), 0.f);
    long long gid = load_idx(batch, node, g_b64);
    float* p = &out[(size_t)gid * F + c];
    asm volatile("red.global.add.v4.f32 [%0], {%1,%2,%3,%4};"
                 :: "l"(p), "f"(o.x), "f"(o.y), "f"(o.z), "f"(o.w) : "memory");
    if ((i & 31) == 0) atomicAdd(&g_counts[gid], 1);
}

__global__ void div_kernel(float* __restrict__ out, int gtot) {
    int i = blockIdx.x * blockDim.x + threadIdx.x;
    if (i >= gtot * F) return;
    int gidx = i >> 7;
    float cnt = (float)max(g_counts[gidx], 1);
    out[i] = out[i] / cnt;
}

// ---------------- launch ----------------
extern "C" void kernel_launch(void* const* d_in, const int* in_sizes, int n_in,
                              void* d_out, int out_size) {
    const float* x    = (const float*)d_in[0];
    const void*  edge = d_in[1];
    const void*  batch= d_in[2];
    const float* W1   = (const float*)d_in[3];
    const float* b1   = (const float*)d_in[4];
    const float* W2   = (const float*)d_in[5];
    const float* b2   = (const float*)d_in[6];
    float* out = (float*)d_out;

    int N = in_sizes[0] / F;
    int E = in_sizes[1] / 2;
    int G = out_size / F;

    float *p_g, *p_acc, *p_degc, *p_counts;
    cudaGetSymbolAddress((void**)&p_g, g_g);
    cudaGetSymbolAddress((void**)&p_acc, g_acc);
    cudaGetSymbolAddress((void**)&p_degc, g_degc);
    cudaGetSymbolAddress((void**)&p_counts, g_counts);

    const int TB = 256;
    long long nf = (long long)N * F;           // multiple of 4
    int zb_big  = (int)((nf / 4 + TB - 1) / TB);

    // dtype detection (values fit int32 -> high words all zero iff int64)
    detect_kernel<<<1, 256>>>((const int*)edge, 2048, 0);
    detect_kernel<<<1, 256>>>((const int*)batch, 2048, 1);

    // degrees
    long long ndeg = (N + 3) & ~3LL;
    zero_kernel<<<(int)((ndeg / 4 + TB - 1) / TB), TB>>>((float*)p_degc, ndeg);
    deg_kernel<<<(E + TB - 1) / TB, TB>>>(edge, E);
    dis_kernel<<<(N + TB - 1) / TB, TB>>>(N);

    // layer 1
    gemm_scale_kernel<<<(N + 63) / 64, 256>>>(x, W1, p_g, N);
    zero_kernel<<<zb_big, TB>>>(p_acc, nf);
    scatter_kernel<<<(E + 7) / 8, TB>>>(p_g, p_acc, edge, E);
    finish1_kernel<<<(N * 32 + TB - 1) / TB, TB>>>(b1, N);

    // layer 2
    gemm_scale_kernel<<<(N + 63) / 64, 256>>>(p_acc, W2, p_g, N);
    zero_kernel<<<zb_big, TB>>>(p_acc, nf);
    scatter_kernel<<<(E + 7) / 8, TB>>>(p_g, p_acc, edge, E);

    // pooling
    zero_kernel<<<(G * F / 4 + TB - 1) / TB, TB>>>(out, (long long)G * F);
    zero_kernel<<<1, TB>>>((float*)p_counts, 1024);
    finish2_kernel<<<(N * 32 + TB - 1) / TB, TB>>>(batch, b2, out, N);
    div_kernel<<<(G * F + TB - 1) / TB, TB>>>(out, G);
}

// round 3
// speedup vs baseline: 1.9038x; 1.9038x over previous
#include <cuda_runtime.h>
#include <cuda_bf16.h>
#include <stdint.h>

// ---------------- static scratch (no allocation allowed) ----------------
#define N_MAX 100352          // >= N=100000
#define E_MAX 1700000         // >= E=1600000
#define F 128                 // feature dim (IN=HID=OUT=128)

__device__ __align__(16) static float g_g[(size_t)N_MAX * F];    // pre-scaled transformed features
__device__ __align__(16) static float g_acc[(size_t)N_MAX * F];  // h1 / aggregation output
__device__ __align__(16) static float g_dis[N_MAX];
__device__ static int   g_degc[N_MAX];
__device__ static int   g_rowptr[N_MAX + 4];
__device__ static int   g_cursor[N_MAX];
__device__ static int   g_csr[E_MAX];
__device__ static int   g_part[256];
__device__ static int   g_counts[1024];
__device__ static int   g_e64;   // 1 if edge_index is int64
__device__ static int   g_b64;   // 1 if batch is int64

// ---------------- dtype detection ----------------
__global__ void detect_kernel(const int* __restrict__ a, int nwords, int which) {
    __shared__ int any;
    if (threadIdx.x == 0) any = 0;
    __syncthreads();
    int local = 0;
    for (int i = 1 + 2 * (int)threadIdx.x; i < nwords; i += 2 * (int)blockDim.x)
        local |= a[i];
    if (local) atomicOr(&any, 1);
    __syncthreads();
    if (threadIdx.x == 0) {
        int is64 = (any == 0) ? 1 : 0;
        if (which == 0) g_e64 = is64; else g_b64 = is64;
    }
}

__device__ __forceinline__ long long load_idx(const void* p, long long i, int is64) {
    if (is64) return ((const long long*)p)[i];
    return (long long)((const int*)p)[i];
}

// ---------------- zero fill (n = count of 4-byte words, multiple of 4) ------
__global__ void zero_kernel(float* __restrict__ p, long long n) {
    long long i = (long long)blockIdx.x * blockDim.x + threadIdx.x;
    if (i * 4 < n) *(float4*)(p + i * 4) = make_float4(0.f, 0.f, 0.f, 0.f);
}

// ---------------- degree / dis ----------------
__global__ void deg_kernel(const void* __restrict__ edge, int E) {
    int e = blockIdx.x * blockDim.x + threadIdx.x;
    if (e >= E) return;
    long long dst = load_idx(edge, (long long)E + e, g_e64);
    atomicAdd(&g_degc[dst], 1);
}

__global__ void dis_kernel(int n) {
    int i = blockIdx.x * blockDim.x + threadIdx.x;
    if (i >= n) return;
    g_dis[i] = rsqrtf((float)(g_degc[i] + 1));   // +1 self loop, always > 0
}

// ---------------- CSR build: 2-level exclusive scan + fill ----------------
__global__ void scan1_kernel(int n) {                 // block = 1024
    __shared__ int sh[1024];
    int t = threadIdx.x;
    int i = blockIdx.x * 1024 + t;
    int v = (i < n) ? g_degc[i] : 0;
    sh[t] = v;
    __syncthreads();
    for (int off = 1; off < 1024; off <<= 1) {
        int tmp = (t >= off) ? sh[t - off] : 0;
        __syncthreads();
        sh[t] += tmp;
        __syncthreads();
    }
    if (i < n) g_rowptr[i] = sh[t] - v;               // block-local exclusive
    if (t == 1023) g_part[blockIdx.x] = sh[1023];
}

__global__ void scan2_kernel(int nblk) {              // 1 block of 256
    __shared__ int sh[256];
    int t = threadIdx.x;
    int v = (t < nblk) ? g_part[t] : 0;
    sh[t] = v;
    __syncthreads();
    for (int off = 1; off < 256; off <<= 1) {
        int tmp = (t >= off) ? sh[t - off] : 0;
        __syncthreads();
        sh[t] += tmp;
        __syncthreads();
    }
    g_part[t] = sh[t] - v;                            // exclusive
}

__global__ void scan3_kernel(int n) {                 // block = 1024
    int i = blockIdx.x * 1024 + threadIdx.x;
    if (i >= n) return;
    int r = g_rowptr[i] + g_part[blockIdx.x];
    g_rowptr[i] = r;
    g_cursor[i] = r;
    if (i == n - 1) g_rowptr[n] = r + g_degc[i];
}

__global__ void fill_kernel(const void* __restrict__ edge, int E) {
    int e = blockIdx.x * blockDim.x + threadIdx.x;
    if (e >= E) return;
    int is64 = g_e64;
    long long src = load_idx(edge, e, is64);
    long long dst = load_idx(edge, (long long)E + e, is64);
    int p = atomicAdd(&g_cursor[dst], 1);
    g_csr[p] = (int)src;
}

// ---------------- GEMM: C[i][:] = (A[i][:] @ W) * dis[i] ----------------
__global__ void __launch_bounds__(256) gemm_scale_kernel(
    const float* __restrict__ A, const float* __restrict__ W,
    float* __restrict__ C, int n)
{
    __shared__ float As[64 * F];
    int t = threadIdx.x;
    int row0 = blockIdx.x * 64;

    for (int i = t; i < 64 * F / 4; i += 256) {
        int lin = i * 4;
        int r = lin >> 7;
        int c = lin & 127;
        float4 v = make_float4(0.f, 0.f, 0.f, 0.f);
        if (row0 + r < n) v = *(const float4*)&A[(size_t)(row0 + r) * F + c];
        *(float4*)&As[lin] = v;
    }
    __syncthreads();

    int tx = t & 31;
    int ty = t >> 5;

    float acc[8][4];
#pragma unroll
    for (int r = 0; r < 8; r++)
#pragma unroll
        for (int c = 0; c < 4; c++) acc[r][c] = 0.f;

#pragma unroll 2
    for (int k0 = 0; k0 < F; k0 += 4) {
        float4 w0 = __ldg((const float4*)&W[(size_t)(k0 + 0) * F + tx * 4]);
        float4 w1 = __ldg((const float4*)&W[(size_t)(k0 + 1) * F + tx * 4]);
        float4 w2 = __ldg((const float4*)&W[(size_t)(k0 + 2) * F + tx * 4]);
        float4 w3 = __ldg((const float4*)&W[(size_t)(k0 + 3) * F + tx * 4]);
#pragma unroll
        for (int r = 0; r < 8; r++) {
            float4 a = *(const float4*)&As[(ty * 8 + r) * F + k0];
            acc[r][0] += a.x * w0.x + a.y * w1.x + a.z * w2.x + a.w * w3.x;
            acc[r][1] += a.x * w0.y + a.y * w1.y + a.z * w2.y + a.w * w3.y;
            acc[r][2] += a.x * w0.z + a.y * w1.z + a.z * w2.z + a.w * w3.z;
            acc[r][3] += a.x * w0.w + a.y * w1.w + a.z * w2.w + a.w * w3.w;
        }
    }

#pragma unroll
    for (int r = 0; r < 8; r++) {
        int row = row0 + ty * 8 + r;
        if (row < n) {
            float s = g_dis[row];
            float4 o = make_float4(acc[r][0] * s, acc[r][1] * s, acc[r][2] * s, acc[r][3] * s);
            *(float4*)&C[(size_t)row * F + tx * 4] = o;
        }
    }
}

// ---------------- CSR aggregation + fused epilogue -------------------------
// warp per node: sum = g[node] + sum_{src in CSR row} g[src]
// out = relu(dis[node] * sum + b)
__device__ __forceinline__ float4 agg_row(int node, int lane) {
    const float4* gp = (const float4*)g_g;
    float4 s = gp[(size_t)node * 32 + lane];          // self loop
    int i = g_rowptr[node];
    int end = g_rowptr[node + 1];
    for (; i + 4 <= end; i += 4) {
        int s0 = __ldg(&g_csr[i + 0]);
        int s1 = __ldg(&g_csr[i + 1]);
        int s2 = __ldg(&g_csr[i + 2]);
        int s3 = __ldg(&g_csr[i + 3]);
        float4 v0 = gp[(size_t)s0 * 32 + lane];
        float4 v1 = gp[(size_t)s1 * 32 + lane];
        float4 v2 = gp[(size_t)s2 * 32 + lane];
        float4 v3 = gp[(size_t)s3 * 32 + lane];
        s.x += v0.x + v1.x + v2.x + v3.x;
        s.y += v0.y + v1.y + v2.y + v3.y;
        s.z += v0.z + v1.z + v2.z + v3.z;
        s.w += v0.w + v1.w + v2.w + v3.w;
    }
    for (; i < end; i++) {
        int s0 = __ldg(&g_csr[i]);
        float4 v0 = gp[(size_t)s0 * 32 + lane];
        s.x += v0.x; s.y += v0.y; s.z += v0.z; s.w += v0.w;
    }
    return s;
}

__global__ void __launch_bounds__(256) agg1_kernel(const float* __restrict__ b, int n) {
    int w = (blockIdx.x * blockDim.x + threadIdx.x) >> 5;
    int lane = threadIdx.x & 31;
    if (w >= n) return;
    float4 s = agg_row(w, lane);
    float d = g_dis[w];
    float4 bb = *(const float4*)&b[lane * 4];
    float4 o;
    o.x = fmaxf(fmaf(d, s.x, bb.x), 0.f);
    o.y = fmaxf(fmaf(d, s.y, bb.y), 0.f);
    o.z = fmaxf(fmaf(d, s.z, bb.z), 0.f);
    o.w = fmaxf(fmaf(d, s.w, bb.w), 0.f);
    *(float4*)&g_acc[((size_t)w * 32 + lane) * 4] = o;
}

__global__ void __launch_bounds__(256) agg2_kernel(
    const void* __restrict__ batch, const float* __restrict__ b,
    float* __restrict__ out, int n)
{
    int w = (blockIdx.x * blockDim.x + threadIdx.x) >> 5;
    int lane = threadIdx.x & 31;
    if (w >= n) return;
    float4 s = agg_row(w, lane);
    float d = g_dis[w];
    float4 bb = *(const float4*)&b[lane * 4];
    float4 o;
    o.x = fmaxf(fmaf(d, s.x, bb.x), 0.f);
    o.y = fmaxf(fmaf(d, s.y, bb.y), 0.f);
    o.z = fmaxf(fmaf(d, s.z, bb.z), 0.f);
    o.w = fmaxf(fmaf(d, s.w, bb.w), 0.f);
    long long gid = load_idx(batch, w, g_b64);
    float* p = &out[(size_t)gid * F + lane * 4];
    asm volatile("red.global.add.v4.f32 [%0], {%1,%2,%3,%4};"
                 :: "l"(p), "f"(o.x), "f"(o.y), "f"(o.z), "f"(o.w) : "memory");
    if (lane == 0) atomicAdd(&g_counts[gid], 1);
}

__global__ void div_kernel(float* __restrict__ out, int gtot) {
    int i = blockIdx.x * blockDim.x + threadIdx.x;
    if (i >= gtot * F) return;
    int gidx = i >> 7;
    float cnt = (float)max(g_counts[gidx], 1);
    out[i] = out[i] / cnt;
}

// ---------------- launch ----------------
extern "C" void kernel_launch(void* const* d_in, const int* in_sizes, int n_in,
                              void* d_out, int out_size) {
    const float* x    = (const float*)d_in[0];
    const void*  edge = d_in[1];
    const void*  batch= d_in[2];
    const float* W1   = (const float*)d_in[3];
    const float* b1   = (const float*)d_in[4];
    const float* W2   = (const float*)d_in[5];
    const float* b2   = (const float*)d_in[6];
    float* out = (float*)d_out;

    int N = in_sizes[0] / F;
    int E = in_sizes[1] / 2;
    int G = out_size / F;

    float *p_g, *p_acc, *p_degc, *p_counts;
    cudaGetSymbolAddress((void**)&p_g, g_g);
    cudaGetSymbolAddress((void**)&p_acc, g_acc);
    cudaGetSymbolAddress((void**)&p_degc, g_degc);
    cudaGetSymbolAddress((void**)&p_counts, g_counts);

    const int TB = 256;

    // dtype detection
    detect_kernel<<<1, 256>>>((const int*)edge, 2048, 0);
    detect_kernel<<<1, 256>>>((const int*)batch, 2048, 1);

    // degrees + dis
    long long ndeg = (N + 3) & ~3LL;
    zero_kernel<<<(int)((ndeg / 4 + TB - 1) / TB), TB>>>((float*)p_degc, ndeg);
    deg_kernel<<<(E + TB - 1) / TB, TB>>>(edge, E);
    dis_kernel<<<(N + TB - 1) / TB, TB>>>(N);

    // CSR build
    int nblk = (N + 1023) / 1024;
    scan1_kernel<<<nblk, 1024>>>(N);
    scan2_kernel<<<1, 256>>>(nblk);
    scan3_kernel<<<nblk, 1024>>>(N);
    fill_kernel<<<(E + TB - 1) / TB, TB>>>(edge, E);

    int agg_grid = (N + 7) / 8;

    // layer 1
    gemm_scale_kernel<<<(N + 63) / 64, 256>>>(x, W1, p_g, N);
    agg1_kernel<<<agg_grid, 256>>>(b1, N);

    // layer 2
    gemm_scale_kernel<<<(N + 63) / 64, 256>>>(p_acc, W2, p_g, N);
    zero_kernel<<<(G * F / 4 + TB - 1) / TB, TB>>>(out, (long long)G * F);
    zero_kernel<<<1, TB>>>((float*)p_counts, 1024);
    agg2_kernel<<<agg_grid, 256>>>(batch, b2, out, N);
    div_kernel<<<(G * F + TB - 1) / TB, TB>>>(out, G);
}

// round 4
// speedup vs baseline: 2.8782x; 1.5119x over previous
#include <cuda_runtime.h>
#include <cuda_fp16.h>
#include <cuda_bf16.h>
#include <stdint.h>

// ---------------- static scratch (no allocation allowed) ----------------
#define N_MAX 100352          // >= N=100000
#define E_MAX 1700000         // >= E=1600000
#define F 128                 // feature dim (IN=HID=OUT=128)
#define SA 136                // padded smem row stride (halves); 136*2=272B = 17*16B

__device__ __align__(16) static __half g_gh[(size_t)N_MAX * F];  // pre-scaled transformed features (fp16)
__device__ __align__(16) static __half g_h1[(size_t)N_MAX * F];  // layer-1 output (fp16)
__device__ __align__(16) static float g_dis[N_MAX];
__device__ static int   g_degc[N_MAX];
__device__ static int   g_rowptr[N_MAX + 4];
__device__ static int   g_cursor[N_MAX];
__device__ static int   g_csr[E_MAX];
__device__ static int   g_part[256];
__device__ static int   g_counts[1024];
__device__ static int   g_e64;   // 1 if edge_index is int64
__device__ static int   g_b64;   // 1 if batch is int64

// ---------------- dtype detection ----------------
__global__ void detect_kernel(const int* __restrict__ a, int nwords, int which) {
    __shared__ int any;
    if (threadIdx.x == 0) any = 0;
    __syncthreads();
    int local = 0;
    for (int i = 1 + 2 * (int)threadIdx.x; i < nwords; i += 2 * (int)blockDim.x)
        local |= a[i];
    if (local) atomicOr(&any, 1);
    __syncthreads();
    if (threadIdx.x == 0) {
        int is64 = (any == 0) ? 1 : 0;
        if (which == 0) g_e64 = is64; else g_b64 = is64;
    }
}

__device__ __forceinline__ long long load_idx(const void* p, long long i, int is64) {
    if (is64) return ((const long long*)p)[i];
    return (long long)((const int*)p)[i];
}

// ---------------- zero fill (n = count of 4-byte words, multiple of 4) ------
__global__ void zero_kernel(float* __restrict__ p, long long n) {
    long long i = (long long)blockIdx.x * blockDim.x + threadIdx.x;
    if (i * 4 < n) *(float4*)(p + i * 4) = make_float4(0.f, 0.f, 0.f, 0.f);
}

// ---------------- degree / dis ----------------
__global__ void deg_kernel(const void* __restrict__ edge, int E) {
    int e = blockIdx.x * blockDim.x + threadIdx.x;
    if (e >= E) return;
    long long dst = load_idx(edge, (long long)E + e, g_e64);
    atomicAdd(&g_degc[dst], 1);
}

__global__ void dis_kernel(int n) {
    int i = blockIdx.x * blockDim.x + threadIdx.x;
    if (i >= n) return;
    g_dis[i] = rsqrtf((float)(g_degc[i] + 1));   // +1 self loop, always > 0
}

// ---------------- CSR build: 2-level exclusive scan + fill ----------------
__global__ void scan1_kernel(int n) {                 // block = 1024
    __shared__ int sh[1024];
    int t = threadIdx.x;
    int i = blockIdx.x * 1024 + t;
    int v = (i < n) ? g_degc[i] : 0;
    sh[t] = v;
    __syncthreads();
    for (int off = 1; off < 1024; off <<= 1) {
        int tmp = (t >= off) ? sh[t - off] : 0;
        __syncthreads();
        sh[t] += tmp;
        __syncthreads();
    }
    if (i < n) g_rowptr[i] = sh[t] - v;               // block-local exclusive
    if (t == 1023) g_part[blockIdx.x] = sh[1023];
}

__global__ void scan2_kernel(int nblk) {              // 1 block of 256
    __shared__ int sh[256];
    int t = threadIdx.x;
    int v = (t < nblk) ? g_part[t] : 0;
    sh[t] = v;
    __syncthreads();
    for (int off = 1; off < 256; off <<= 1) {
        int tmp = (t >= off) ? sh[t - off] : 0;
        __syncthreads();
        sh[t] += tmp;
        __syncthreads();
    }
    g_part[t] = sh[t] - v;                            // exclusive
}

__global__ void scan3_kernel(int n) {                 // block = 1024
    int i = blockIdx.x * 1024 + threadIdx.x;
    if (i >= n) return;
    int r = g_rowptr[i] + g_part[blockIdx.x];
    g_rowptr[i] = r;
    g_cursor[i] = r;
    if (i == n - 1) g_rowptr[n] = r + g_degc[i];
}

__global__ void fill_kernel(const void* __restrict__ edge, int E) {
    int e = blockIdx.x * blockDim.x + threadIdx.x;
    if (e >= E) return;
    int is64 = g_e64;
    long long src = load_idx(edge, e, is64);
    long long dst = load_idx(edge, (long long)E + e, is64);
    int p = atomicAdd(&g_cursor[dst], 1);
    g_csr[p] = (int)src;
}

// ---------------- tensor-core GEMM: C[i][:] = fp16((A[i][:] @ W) * dis[i]) --
// block = 256 threads (8 warps), tile 128 rows x 128 cols, K = 128 (one shot)
// warp w computes rows [w*16, w*16+16). mma.sync m16n8k16, fp16 in, fp32 acc.
template<bool A_IS_HALF>
__global__ void __launch_bounds__(256) gemm_mma_kernel(
    const void* __restrict__ Aptr, const float* __restrict__ W,
    __half* __restrict__ C, int n)
{
    extern __shared__ __half sh[];
    __half* As = sh;                 // [128][SA]
    __half* Wt = sh + 128 * SA;      // [128][SA], transposed: Wt[n][k] = W[k][n]

    int t = threadIdx.x;
    int row0 = blockIdx.x * 128;

    // stage W transposed + fp16 (coalesced global read)
    for (int i = t; i < F * F; i += 256) {
        int k = i >> 7, nn = i & 127;
        Wt[nn * SA + k] = __float2half(__ldg(&W[i]));
    }

    // stage A tile -> fp16 smem (zero-pad past n)
    if (A_IS_HALF) {
        const __half* A = (const __half*)Aptr;
        for (int i = t; i < 128 * F / 8; i += 256) {
            int lin = i * 8;
            int r = lin >> 7, c = lin & 127;
            uint4 v = make_uint4(0u, 0u, 0u, 0u);
            if (row0 + r < n) v = *(const uint4*)&A[(size_t)(row0 + r) * F + c];
            *(uint4*)&As[r * SA + c] = v;
        }
    } else {
        const float* A = (const float*)Aptr;
        for (int i = t; i < 128 * F / 4; i += 256) {
            int lin = i * 4;
            int r = lin >> 7, c = lin & 127;
            float4 v = make_float4(0.f, 0.f, 0.f, 0.f);
            if (row0 + r < n) v = *(const float4*)&A[(size_t)(row0 + r) * F + c];
            *(__half2*)&As[r * SA + c]     = __floats2half2_rn(v.x, v.y);
            *(__half2*)&As[r * SA + c + 2] = __floats2half2_rn(v.z, v.w);
        }
    }
    __syncthreads();

    int w = t >> 5, lane = t & 31;
    int gq = lane >> 2, tq = lane & 3;
    int m0 = w * 16;

    float acc[16][4];
#pragma unroll
    for (int nt = 0; nt < 16; nt++)
#pragma unroll
        for (int c = 0; c < 4; c++) acc[nt][c] = 0.f;

#pragma unroll
    for (int k0 = 0; k0 < F; k0 += 16) {
        uint32_t a0 = *(const uint32_t*)&As[(m0 + gq) * SA + k0 + tq * 2];
        uint32_t a1 = *(const uint32_t*)&As[(m0 + gq + 8) * SA + k0 + tq * 2];
        uint32_t a2 = *(const uint32_t*)&As[(m0 + gq) * SA + k0 + tq * 2 + 8];
        uint32_t a3 = *(const uint32_t*)&As[(m0 + gq + 8) * SA + k0 + tq * 2 + 8];
#pragma unroll
        for (int nt = 0; nt < 16; nt++) {
            uint32_t b0 = *(const uint32_t*)&Wt[(nt * 8 + gq) * SA + k0 + tq * 2];
            uint32_t b1 = *(const uint32_t*)&Wt[(nt * 8 + gq) * SA + k0 + tq * 2 + 8];
            asm volatile(
                "mma.sync.aligned.m16n8k16.row.col.f32.f16.f16.f32 "
                "{%0,%1,%2,%3}, {%4,%5,%6,%7}, {%8,%9}, {%0,%1,%2,%3};"
                : "+f"(acc[nt][0]), "+f"(acc[nt][1]), "+f"(acc[nt][2]), "+f"(acc[nt][3])
                : "r"(a0), "r"(a1), "r"(a2), "r"(a3), "r"(b0), "r"(b1));
        }
    }

    int r1 = row0 + m0 + gq;
    int r2 = r1 + 8;
    float d1 = (r1 < n) ? g_dis[r1] : 0.f;
    float d2 = (r2 < n) ? g_dis[r2] : 0.f;
#pragma unroll
    for (int nt = 0; nt < 16; nt++) {
        int col = nt * 8 + tq * 2;
        if (r1 < n) *(__half2*)&C[(size_t)r1 * F + col] = __floats2half2_rn(acc[nt][0] * d1, acc[nt][1] * d1);
        if (r2 < n) *(__half2*)&C[(size_t)r2 * F + col] = __floats2half2_rn(acc[nt][2] * d2, acc[nt][3] * d2);
    }
}

// ---------------- CSR aggregation + fused epilogue (fp16 gather, fp32 acc) --
__device__ __forceinline__ float4 agg_row16(int node, int lane) {
    const uint2* gp = (const uint2*)g_gh;     // 32 uint2 per row (128 halves)
    uint2 u = __ldg(&gp[(size_t)node * 32 + lane]);   // self loop
    float2 f0 = __half22float2(*(const __half2*)&u.x);
    float2 f1 = __half22float2(*(const __half2*)&u.y);
    float4 s = make_float4(f0.x, f0.y, f1.x, f1.y);
    int i = g_rowptr[node];
    int end = g_rowptr[node + 1];
    for (; i + 4 <= end; i += 4) {
        int s0 = __ldg(&g_csr[i + 0]);
        int s1 = __ldg(&g_csr[i + 1]);
        int s2 = __ldg(&g_csr[i + 2]);
        int s3 = __ldg(&g_csr[i + 3]);
        uint2 u0 = __ldg(&gp[(size_t)s0 * 32 + lane]);
        uint2 u1 = __ldg(&gp[(size_t)s1 * 32 + lane]);
        uint2 u2 = __ldg(&gp[(size_t)s2 * 32 + lane]);
        uint2 u3 = __ldg(&gp[(size_t)s3 * 32 + lane]);
        float2 a0 = __half22float2(*(const __half2*)&u0.x);
        float2 b0 = __half22float2(*(const __half2*)&u0.y);
        float2 a1 = __half22float2(*(const __half2*)&u1.x);
        float2 b1 = __half22float2(*(const __half2*)&u1.y);
        float2 a2 = __half22float2(*(const __half2*)&u2.x);
        float2 b2 = __half22float2(*(const __half2*)&u2.y);
        float2 a3 = __half22float2(*(const __half2*)&u3.x);
        float2 b3 = __half22float2(*(const __half2*)&u3.y);
        s.x += a0.x + a1.x + a2.x + a3.x;
        s.y += a0.y + a1.y + a2.y + a3.y;
        s.z += b0.x + b1.x + b2.x + b3.x;
        s.w += b0.y + b1.y + b2.y + b3.y;
    }
    for (; i < end; i++) {
        int s0 = __ldg(&g_csr[i]);
        uint2 u0 = __ldg(&gp[(size_t)s0 * 32 + lane]);
        float2 a0 = __half22float2(*(const __half2*)&u0.x);
        float2 b0 = __half22float2(*(const __half2*)&u0.y);
        s.x += a0.x; s.y += a0.y; s.z += b0.x; s.w += b0.y;
    }
    return s;
}

// warp per node: h1 = fp16(relu(dis*sum + b))
__global__ void __launch_bounds__(256) agg1_kernel(const float* __restrict__ b, int n) {
    int w = (blockIdx.x * blockDim.x + threadIdx.x) >> 5;
    int lane = threadIdx.x & 31;
    if (w >= n) return;
    float4 s = agg_row16(w, lane);
    float d = g_dis[w];
    float4 bb = *(const float4*)&b[lane * 4];
    float ox = fmaxf(fmaf(d, s.x, bb.x), 0.f);
    float oy = fmaxf(fmaf(d, s.y, bb.y), 0.f);
    float oz = fmaxf(fmaf(d, s.z, bb.z), 0.f);
    float ow = fmaxf(fmaf(d, s.w, bb.w), 0.f);
    __half2 p0 = __floats2half2_rn(ox, oy);
    __half2 p1 = __floats2half2_rn(oz, ow);
    uint2 st;
    st.x = *(uint32_t*)&p0;
    st.y = *(uint32_t*)&p1;
    ((uint2*)g_h1)[(size_t)w * 32 + lane] = st;
}

// warp per node: o = relu(dis*sum + b); mean-pool scatter (fp32)
__global__ void __launch_bounds__(256) agg2_kernel(
    const void* __restrict__ batch, const float* __restrict__ b,
    float* __restrict__ out, int n)
{
    int w = (blockIdx.x * blockDim.x + threadIdx.x) >> 5;
    int lane = threadIdx.x & 31;
    if (w >= n) return;
    float4 s = agg_row16(w, lane);
    float d = g_dis[w];
    float4 bb = *(const float4*)&b[lane * 4];
    float4 o;
    o.x = fmaxf(fmaf(d, s.x, bb.x), 0.f);
    o.y = fmaxf(fmaf(d, s.y, bb.y), 0.f);
    o.z = fmaxf(fmaf(d, s.z, bb.z), 0.f);
    o.w = fmaxf(fmaf(d, s.w, bb.w), 0.f);
    long long gid = load_idx(batch, w, g_b64);
    float* p = &out[(size_t)gid * F + lane * 4];
    asm volatile("red.global.add.v4.f32 [%0], {%1,%2,%3,%4};"
                 :: "l"(p), "f"(o.x), "f"(o.y), "f"(o.z), "f"(o.w) : "memory");
    if (lane == 0) atomicAdd(&g_counts[gid], 1);
}

__global__ void div_kernel(float* __restrict__ out, int gtot) {
    int i = blockIdx.x * blockDim.x + threadIdx.x;
    if (i >= gtot * F) return;
    int gidx = i >> 7;
    float cnt = (float)max(g_counts[gidx], 1);
    out[i] = out[i] / cnt;
}

// ---------------- launch ----------------
extern "C" void kernel_launch(void* const* d_in, const int* in_sizes, int n_in,
                              void* d_out, int out_size) {
    const float* x    = (const float*)d_in[0];
    const void*  edge = d_in[1];
    const void*  batch= d_in[2];
    const float* W1   = (const float*)d_in[3];
    const float* b1   = (const float*)d_in[4];
    const float* W2   = (const float*)d_in[5];
    const float* b2   = (const float*)d_in[6];
    float* out = (float*)d_out;

    int N = in_sizes[0] / F;
    int E = in_sizes[1] / 2;
    int G = out_size / F;

    void *p_gh, *p_h1, *p_degc, *p_counts;
    cudaGetSymbolAddress(&p_gh, g_gh);
    cudaGetSymbolAddress(&p_h1, g_h1);
    cudaGetSymbolAddress(&p_degc, g_degc);
    cudaGetSymbolAddress(&p_counts, g_counts);

    const int SMEM = 2 * 128 * SA * (int)sizeof(__half);   // 69632 bytes
    cudaFuncSetAttribute(gemm_mma_kernel<false>, cudaFuncAttributeMaxDynamicSharedMemorySize, SMEM);
    cudaFuncSetAttribute(gemm_mma_kernel<true>,  cudaFuncAttributeMaxDynamicSharedMemorySize, SMEM);

    const int TB = 256;

    // dtype detection
    detect_kernel<<<1, 256>>>((const int*)edge, 2048, 0);
    detect_kernel<<<1, 256>>>((const int*)batch, 2048, 1);

    // degrees + dis
    long long ndeg = (N + 3) & ~3LL;
    zero_kernel<<<(int)((ndeg / 4 + TB - 1) / TB), TB>>>((float*)p_degc, ndeg);
    deg_kernel<<<(E + TB - 1) / TB, TB>>>(edge, E);
    dis_kernel<<<(N + TB - 1) / TB, TB>>>(N);

    // CSR build
    int nblk = (N + 1023) / 1024;
    scan1_kernel<<<nblk, 1024>>>(N);
    scan2_kernel<<<1, 256>>>(nblk);
    scan3_kernel<<<nblk, 1024>>>(N);
    fill_kernel<<<(E + TB - 1) / TB, TB>>>(edge, E);

    int agg_grid = (N + 7) / 8;
    int gemm_grid = (N + 127) / 128;

    // layer 1
    gemm_mma_kernel<false><<<gemm_grid, 256, SMEM>>>(x, W1, (__half*)p_gh, N);
    agg1_kernel<<<agg_grid, 256>>>(b1, N);

    // layer 2
    gemm_mma_kernel<true><<<gemm_grid, 256, SMEM>>>(p_h1, W2, (__half*)p_gh, N);
    zero_kernel<<<(G * F / 4 + TB - 1) / TB, TB>>>(out, (long long)G * F);
    zero_kernel<<<1, TB>>>((float*)p_counts, 1024);
    agg2_kernel<<<agg_grid, 256>>>(batch, b2, out, N);
    div_kernel<<<(G * F + TB - 1) / TB, TB>>>(out, G);
}